// round 12
// baseline (speedup 1.0000x reference)
#include <cuda_runtime.h>
#include <math.h>

#define IN_DIM 8
#define HID 50
#define BATCH 4096
#define TLEN 512
#define ROWS 150
#define RPAD 164
#define NB 32
#define NT 256
#define GRIDN (BATCH / NB)
#define HS (HID * NB)      // one h buffer
#define XS (IN_DIM * NB)   // one x buffer
#define WPROW 256          // Wp row stride: 32 tiles * 8 floats
#define KCH 6              // h-part k=0..5 cached in regs

typedef unsigned long long ull;

__device__ __forceinline__ ull pk2(float a) {
    ull r; asm("mov.b64 %0, {%1, %1};" : "=l"(r) : "f"(a)); return r;
}
__device__ __forceinline__ ull mk2(float lo, float hi) {
    ull r; asm("mov.b64 %0, {%1, %2};" : "=l"(r) : "f"(lo), "f"(hi)); return r;
}
__device__ __forceinline__ ull ff2(ull a, ull b, ull c) {
    ull d; asm("fma.rn.f32x2 %0, %1, %2, %3;" : "=l"(d) : "l"(a), "l"(b), "l"(c));
    return d;
}
__device__ __forceinline__ ull add2(ull a, ull b) {
    ull d; asm("add.rn.f32x2 %0, %1, %2;" : "=l"(d) : "l"(a), "l"(b));
    return d;
}
__device__ __forceinline__ float2 up2(ull v) {
    float2 r; asm("mov.b64 {%0, %1}, %2;" : "=f"(r.x), "=f"(r.y) : "l"(v)); return r;
}
__device__ __forceinline__ float tanhapx(float v) {
    float r; asm("tanh.approx.f32 %0, %1;" : "=f"(r) : "f"(v)); return r;
}
__device__ __forceinline__ float fsig(float v) {
    return fmaf(0.5f, tanhapx(0.5f * v), 0.5f);
}

__global__ __launch_bounds__(NT, 1) void gru_kernel(
    const float* __restrict__ x, const float* __restrict__ W_ih,
    const float* __restrict__ W_hh, const float* __restrict__ b_ih,
    const float* __restrict__ b_hh, const float* __restrict__ W_out,
    const float* __restrict__ b_out, float* __restrict__ out)
{
    extern __shared__ float sm[];
    float* Wp  = sm;                    // [HID][32 tiles][8]: W_hh only
    float* bi  = Wp  + HID * WPROW;     // [RPAD] b_ih (zero-padded)
    float* bh  = bi  + RPAD;            // [RPAD] b_hh
    float* hx  = bh  + RPAD;            // [2][HID][NB]
    float* xsh = hx  + 2 * HS;          // [2][IN_DIM][NB]: x(s) lives in slot s&1

    const int tid  = threadIdx.x;
    const int lane = tid & 31;
    const int wid  = tid >> 5;
    const int b0   = blockIdx.x * NB;
    const int tile = wid * 4 + (lane >> 3);   // 0..31 (25 live)
    const int c    = tile * 2;
    const int tb4  = (lane & 7) * 4;
    const bool live = (c < HID);

    // ---- one-time: pack W_hh gate-interleaved per tile ----
    for (int i = tid; i < HID * WPROW; i += NT) {
        int k = i >> 8;
        int r = i & 255;
        int tl = r >> 3;
        int g  = (r & 7) >> 1;
        int u  = r & 1;
        int cu = tl * 2 + u;
        float v = 0.0f;
        if (g < 3 && cu < HID) v = W_hh[(g * HID + cu) * HID + k];
        Wp[i] = v;
    }
    for (int j = tid; j < RPAD; j += NT) {
        bi[j] = (j < ROWS) ? b_ih[j] : 0.0f;
        bh[j] = (j < ROWS) ? b_hh[j] : 0.0f;
    }
    for (int i = tid; i < HS; i += NT) hx[i] = 0.0f;   // h(0) = 0, buffer 0

    // ---- x-part weights entirely in registers (from gmem) ----
    ull cwx_r[IN_DIM], cwx_z[IN_DIM], cwx_n[IN_DIM];
    #pragma unroll
    for (int j = 0; j < IN_DIM; j++) {
        if (live) {
            cwx_r[j] = mk2(W_ih[c * IN_DIM + j],           W_ih[(c + 1) * IN_DIM + j]);
            cwx_z[j] = mk2(W_ih[(HID + c) * IN_DIM + j],   W_ih[(HID + c + 1) * IN_DIM + j]);
            cwx_n[j] = mk2(W_ih[(2*HID + c) * IN_DIM + j], W_ih[(2*HID + c + 1) * IN_DIM + j]);
        } else {
            cwx_r[j] = 0ULL; cwx_z[j] = 0ULL; cwx_n[j] = 0ULL;
        }
    }

    // ---- warp 7: x duty (2 steps ahead). Publish x0->slot0, x1->slot1; hold x2 ----
    float4 xa, xb;
    const float* xrow = nullptr;
    if (wid == 7) {
        xrow = x + (size_t)(b0 + lane) * TLEN * IN_DIM;
        float4 a0 = *(const float4*)&xrow[0];
        float4 a1 = *(const float4*)&xrow[4];
        #pragma unroll
        for (int j = 0; j < 4; j++) {
            xsh[j * NB + lane]       = ((const float*)&a0)[j];
            xsh[(j + 4) * NB + lane] = ((const float*)&a1)[j];
        }
        a0 = *(const float4*)&xrow[IN_DIM];
        a1 = *(const float4*)&xrow[IN_DIM + 4];
        #pragma unroll
        for (int j = 0; j < 4; j++) {
            xsh[XS + j * NB + lane]       = ((const float*)&a0)[j];
            xsh[XS + (j + 4) * NB + lane] = ((const float*)&a1)[j];
        }
        xa = *(const float4*)&xrow[2 * IN_DIM];
        xb = *(const float4*)&xrow[2 * IN_DIM + 4];
    }
    __syncthreads();

    // bias ulls
    ull bsi[3], bbh[3];
    #pragma unroll
    for (int g = 0; g < 3; g++) {
        bsi[g] = *(const ull*)&bi[c + 50 * g];
        bbh[g] = *(const ull*)&bh[c + 50 * g];
    }

    // h-part register cache k=0..KCH-1
    ulonglong2 cwh_rz[KCH]; ull cwh_n[KCH];
    #pragma unroll
    for (int j = 0; j < KCH; j++) {
        const float* wrow = &Wp[(j * 32 + tile) * 8];
        cwh_rz[j] = *(const ulonglong2*)wrow;
        cwh_n[j]  = *(const ull*)(wrow + 4);
    }

    // persistent across steps: acc (x-part of next step), gis (gi_n snapshot)
    ull acc[3][4], gis[4];

    // ---- prologue x-part for t=0 (reads xsh slot 0) ----
    if (wid != 7) {
        #pragma unroll
        for (int g = 0; g < 3; g++)
            #pragma unroll
            for (int v = 0; v < 4; v++) acc[g][v] = bsi[g];
        #pragma unroll
        for (int j = 0; j < IN_DIM; j++) {
            float4 hq = *(const float4*)&xsh[j * NB + tb4];
            ull hp[4] = {pk2(hq.x), pk2(hq.y), pk2(hq.z), pk2(hq.w)};
            #pragma unroll
            for (int v = 0; v < 4; v++) {
                acc[0][v] = ff2(hp[v], cwx_r[j], acc[0][v]);
                acc[1][v] = ff2(hp[v], cwx_z[j], acc[1][v]);
                acc[2][v] = ff2(hp[v], cwx_n[j], acc[2][v]);
            }
        }
        #pragma unroll
        for (int v = 0; v < 4; v++) gis[v] = acc[2][v];
        #pragma unroll
        for (int g = 0; g < 3; g++)
            #pragma unroll
            for (int v = 0; v < 4; v++) acc[g][v] = add2(acc[g][v], bbh[g]);
    }
    __syncthreads();   // protect xsh slot 0 from warp7's t=0 overwrite

    for (int t = 0; t < TLEN; t++) {
        float* hcur = hx + (t & 1) * HS;
        float* hnxt = hx + ((t + 1) & 1) * HS;

        if (wid != 7) {
            // ---- h-part k=0..KCH-1 (W in regs) ----
            #pragma unroll
            for (int j = 0; j < KCH; j++) {
                float4 hq = *(const float4*)&hcur[j * NB + tb4];
                ull hp[4] = {pk2(hq.x), pk2(hq.y), pk2(hq.z), pk2(hq.w)};
                #pragma unroll
                for (int v = 0; v < 4; v++) {
                    acc[0][v] = ff2(hp[v], cwh_rz[j].x, acc[0][v]);
                    acc[1][v] = ff2(hp[v], cwh_rz[j].y, acc[1][v]);
                    acc[2][v] = ff2(hp[v], cwh_n[j],    acc[2][v]);
                }
            }
            // ---- h-part k=KCH..49 (W from smem) ----
            #pragma unroll
            for (int k = KCH; k < HID; k++) {
                const float* wrow = &Wp[(k * 32 + tile) * 8];
                ulonglong2 wrz = *(const ulonglong2*)wrow;
                ull wn = *(const ull*)(wrow + 4);
                float4 hq = *(const float4*)&hcur[k * NB + tb4];
                ull hp[4] = {pk2(hq.x), pk2(hq.y), pk2(hq.z), pk2(hq.w)};
                #pragma unroll
                for (int v = 0; v < 4; v++) {
                    acc[0][v] = ff2(hp[v], wrz.x, acc[0][v]);
                    acc[1][v] = ff2(hp[v], wrz.y, acc[1][v]);
                    acc[2][v] = ff2(hp[v], wn,    acc[2][v]);
                }
            }

            // ---- gates; write h(t+1) ----
            if (live) {
                float4 ho0 = *(const float4*)&hcur[c * NB + tb4];
                float4 ho1 = *(const float4*)&hcur[(c + 1) * NB + tb4];
                const float* o0 = (const float*)&ho0;
                const float* o1 = (const float*)&ho1;
                float hn0[4], hn1[4];
                #pragma unroll
                for (int v = 0; v < 4; v++) {
                    float2 sr = up2(acc[0][v]);
                    float2 sz = up2(acc[1][v]);
                    float2 sn = up2(acc[2][v]);
                    float2 gi = up2(gis[v]);
                    float r0 = fsig(sr.x), z0 = fsig(sz.x);
                    float n0 = tanhapx(sn.x + (r0 - 1.0f) * (sn.x - gi.x));
                    hn0[v] = n0 + z0 * (o0[v] - n0);
                    float r1 = fsig(sr.y), z1 = fsig(sz.y);
                    float n1 = tanhapx(sn.y + (r1 - 1.0f) * (sn.y - gi.y));
                    hn1[v] = n1 + z1 * (o1[v] - n1);
                }
                *(float4*)&hnxt[c * NB + tb4]       = make_float4(hn0[0], hn0[1], hn0[2], hn0[3]);
                *(float4*)&hnxt[(c + 1) * NB + tb4] = make_float4(hn1[0], hn1[1], hn1[2], hn1[3]);
            }

            // ---- x-part for step t+1 (reads x(t+1) = xsh[(t+1)&1]) ----
            {
                const float* xbuf = xsh + ((t + 1) & 1) * XS;
                #pragma unroll
                for (int g = 0; g < 3; g++)
                    #pragma unroll
                    for (int v = 0; v < 4; v++) acc[g][v] = bsi[g];
                #pragma unroll
                for (int j = 0; j < IN_DIM; j++) {
                    float4 hq = *(const float4*)&xbuf[j * NB + tb4];
                    ull hp[4] = {pk2(hq.x), pk2(hq.y), pk2(hq.z), pk2(hq.w)};
                    #pragma unroll
                    for (int v = 0; v < 4; v++) {
                        acc[0][v] = ff2(hp[v], cwx_r[j], acc[0][v]);
                        acc[1][v] = ff2(hp[v], cwx_z[j], acc[1][v]);
                        acc[2][v] = ff2(hp[v], cwx_n[j], acc[2][v]);
                    }
                }
                #pragma unroll
                for (int v = 0; v < 4; v++) gis[v] = acc[2][v];
                #pragma unroll
                for (int g = 0; g < 3; g++)
                    #pragma unroll
                    for (int v = 0; v < 4; v++) acc[g][v] = add2(acc[g][v], bbh[g]);
            }
        } else {
            // ---- warp 7: publish held x(t+2) into xsh[t&1]; prefetch x(t+3) ----
            if (t + 2 < TLEN) {
                float* xdst = xsh + (t & 1) * XS;
                #pragma unroll
                for (int j = 0; j < 4; j++) {
                    xdst[j * NB + lane]       = ((const float*)&xa)[j];
                    xdst[(j + 4) * NB + lane] = ((const float*)&xb)[j];
                }
                if (t + 3 < TLEN) {
                    xa = *(const float4*)&xrow[(size_t)(t + 3) * IN_DIM];
                    xb = *(const float4*)&xrow[(size_t)(t + 3) * IN_DIM + 4];
                }
            }
        }

        __syncthreads();   // the ONLY per-step barrier
    }

    // final h lives in buffer 0 (TLEN even)
    if (tid < NB) {
        float acc2 = b_out[0];
        #pragma unroll
        for (int cc = 0; cc < HID; cc++) acc2 += hx[cc * NB + tid] * W_out[cc];
        out[b0 + tid] = acc2;
    }
}

extern "C" void kernel_launch(void* const* d_in, const int* in_sizes, int n_in,
                              void* d_out, int out_size) {
    const float* x     = (const float*)d_in[0];
    const float* W_ih  = (const float*)d_in[1];
    const float* W_hh  = (const float*)d_in[2];
    const float* b_ih  = (const float*)d_in[3];
    const float* b_hh  = (const float*)d_in[4];
    const float* W_out = (const float*)d_in[5];
    const float* b_out = (const float*)d_in[6];
    float* out = (float*)d_out;

    size_t smem = (size_t)(HID * WPROW + 2 * RPAD + 2 * HS + 2 * XS) * sizeof(float);
    cudaFuncSetAttribute(gru_kernel,
                         cudaFuncAttributeMaxDynamicSharedMemorySize, (int)smem);
    gru_kernel<<<GRIDN, NT, smem>>>(x, W_ih, W_hh, b_ih, b_hh, W_out, b_out, out);
}

// round 14
// speedup vs baseline: 1.0144x; 1.0144x over previous
#include <cuda_runtime.h>
#include <math.h>

#define IN_DIM 8
#define HID 50
#define BATCH 4096
#define TLEN 512
#define NB 32              // batches per CTA (4 per warp)
#define NT 256
#define GRIDN (BATCH / NB)
#define WKF 256            // Wp floats per k (wrz 128 + wn 64 + pad)
#define HSW 240            // hs floats per warp (58 rows x 4 + pad)
#define KCH 12             // h-part k=0..11 cached in regs

typedef unsigned long long ull;

__device__ __forceinline__ ull pk2(float a) {
    ull r; asm("mov.b64 %0, {%1, %1};" : "=l"(r) : "f"(a)); return r;
}
__device__ __forceinline__ ull mk2(float lo, float hi) {
    ull r; asm("mov.b64 %0, {%1, %2};" : "=l"(r) : "f"(lo), "f"(hi)); return r;
}
__device__ __forceinline__ ull ff2(ull a, ull b, ull c) {
    ull d; asm("fma.rn.f32x2 %0, %1, %2, %3;" : "=l"(d) : "l"(a), "l"(b), "l"(c));
    return d;
}
__device__ __forceinline__ ull add2(ull a, ull b) {
    ull d; asm("add.rn.f32x2 %0, %1, %2;" : "=l"(d) : "l"(a), "l"(b));
    return d;
}
__device__ __forceinline__ float2 up2(ull v) {
    float2 r; asm("mov.b64 {%0, %1}, %2;" : "=f"(r.x), "=f"(r.y) : "l"(v)); return r;
}
__device__ __forceinline__ float tanhapx(float v) {
    float r; asm("tanh.approx.f32 %0, %1;" : "=f"(r) : "f"(v)); return r;
}
__device__ __forceinline__ float fsig(float v) {
    return fmaf(0.5f, tanhapx(0.5f * v), 0.5f);
}

__global__ __launch_bounds__(NT, 1) void gru_kernel(
    const float* __restrict__ x, const float* __restrict__ W_ih,
    const float* __restrict__ W_hh, const float* __restrict__ b_ih,
    const float* __restrict__ b_hh, const float* __restrict__ W_out,
    const float* __restrict__ b_out, float* __restrict__ out)
{
    extern __shared__ float sm[];
    float* Wp = sm;                  // [HID][WKF]  W_hh swizzled (shared by all warps)
    float* hs = Wp + HID * WKF;      // [8 warps][HSW]  warp-private h(0..49) + x(50..57)

    const int tid  = threadIdx.x;
    const int lane = tid & 31;
    const int wid  = tid >> 5;
    const int b0w  = blockIdx.x * NB + wid * 4;   // this warp's 4 batches
    const int c    = lane * 2;                    // lane = c-pair tile (live < 25)
    const bool live = (c < HID);
    float* hw = hs + wid * HSW;

    // per-lane swizzled weight offsets (floats)
    const int wrzOff = (lane & 7) * 4 + (lane >> 3) * 32;          // [0,128)
    const int wnOff  = 128 + (lane & 15) * 2 + (lane >> 4) * 32;   // [128,192)

    // ---- one-time: pack W_hh into swizzled Wp ----
    for (int i = tid; i < HID * WKF; i += NT) {
        int k = i >> 8;
        int r = i & 255;
        float v = 0.0f;
        if (r < 128) {                 // wrz: tile t at (t&7)*4+(t>>3)*32, 4 floats
            int grp = r >> 5, rem = r & 31;
            int t = grp * 8 + (rem >> 2);
            int q = rem & 3;
            int cc = t * 2 + (q & 1);
            int g = q >> 1;            // 0 = r-gate, 1 = z-gate
            if (cc < HID) v = W_hh[(g * HID + cc) * HID + k];
        } else if (r < 192) {          // wn: tile t at 128+(t&15)*2+(t>>4)*32
            int rr = r - 128;
            int grp = rr >> 5, rem = rr & 31;
            int t = grp * 16 + (rem >> 1);
            int cc = t * 2 + (rem & 1);
            if (cc < HID) v = W_hh[(2 * HID + cc) * HID + k];
        }
        Wp[i] = v;
    }

    // ---- warp-private init: zero h rows; x(0) into rows 50-57; prefetch x(1) ----
    for (int i = lane; i < HID * 4; i += 32) hw[i] = 0.0f;
    // lane -> (k = lane>>2, b = lane&3); x slot offset = 200 + lane
    const float* xg = x + (size_t)(b0w + (lane & 3)) * TLEN * IN_DIM + (lane >> 2);
    hw[HID * 4 + lane] = xg[0];
    float xv = xg[IN_DIM];
    __syncthreads();   // Wp visible to all warps (hs is warp-private anyway)

    // ---- per-lane constants in registers ----
    ull bsi[3], bbh[3];
    ull cwx_r[IN_DIM], cwx_z[IN_DIM], cwx_n[IN_DIM];
    #pragma unroll
    for (int g = 0; g < 3; g++) {
        bsi[g] = live ? mk2(b_ih[g * HID + c], b_ih[g * HID + c + 1]) : 0ULL;
        bbh[g] = live ? mk2(b_hh[g * HID + c], b_hh[g * HID + c + 1]) : 0ULL;
    }
    #pragma unroll
    for (int j = 0; j < IN_DIM; j++) {
        if (live) {
            cwx_r[j] = mk2(W_ih[c * IN_DIM + j],             W_ih[(c + 1) * IN_DIM + j]);
            cwx_z[j] = mk2(W_ih[(HID + c) * IN_DIM + j],     W_ih[(HID + c + 1) * IN_DIM + j]);
            cwx_n[j] = mk2(W_ih[(2 * HID + c) * IN_DIM + j], W_ih[(2 * HID + c + 1) * IN_DIM + j]);
        } else { cwx_r[j] = 0ULL; cwx_z[j] = 0ULL; cwx_n[j] = 0ULL; }
    }
    ulonglong2 cwh_rz[KCH]; ull cwh_n[KCH];
    #pragma unroll
    for (int j = 0; j < KCH; j++) {
        cwh_rz[j] = *(const ulonglong2*)&Wp[j * WKF + wrzOff];
        cwh_n[j]  = *(const ull*)&Wp[j * WKF + wnOff];
    }

    for (int t = 0; t < TLEN; t++) {
        // acc[g][v]: gate g, batch v; f32x2 pair = (c, c+1)
        ull acc[3][4];
        #pragma unroll
        for (int g = 0; g < 3; g++)
            #pragma unroll
            for (int v = 0; v < 4; v++) acc[g][v] = bsi[g];

        // ---- x-part: k = 50..57 (x in hs rows 50-57; W in regs) ----
        #pragma unroll
        for (int j = 0; j < IN_DIM; j++) {
            float4 hq = *(const float4*)&hw[(HID + j) * 4];
            ull hp[4] = {pk2(hq.x), pk2(hq.y), pk2(hq.z), pk2(hq.w)};
            #pragma unroll
            for (int v = 0; v < 4; v++) {
                acc[0][v] = ff2(hp[v], cwx_r[j], acc[0][v]);
                acc[1][v] = ff2(hp[v], cwx_z[j], acc[1][v]);
                acc[2][v] = ff2(hp[v], cwx_n[j], acc[2][v]);
            }
        }
        // snapshot gi_n; add b_hh
        ull gis[4];
        #pragma unroll
        for (int v = 0; v < 4; v++) gis[v] = acc[2][v];
        #pragma unroll
        for (int g = 0; g < 3; g++)
            #pragma unroll
            for (int v = 0; v < 4; v++) acc[g][v] = add2(acc[g][v], bbh[g]);

        // ---- h-part k=0..KCH-1 (W in regs) ----
        #pragma unroll
        for (int j = 0; j < KCH; j++) {
            float4 hq = *(const float4*)&hw[j * 4];
            ull hp[4] = {pk2(hq.x), pk2(hq.y), pk2(hq.z), pk2(hq.w)};
            #pragma unroll
            for (int v = 0; v < 4; v++) {
                acc[0][v] = ff2(hp[v], cwh_rz[j].x, acc[0][v]);
                acc[1][v] = ff2(hp[v], cwh_rz[j].y, acc[1][v]);
                acc[2][v] = ff2(hp[v], cwh_n[j],    acc[2][v]);
            }
        }
        // ---- h-part k=KCH..49 (W from swizzled smem) ----
        #pragma unroll
        for (int k = KCH; k < HID; k++) {
            ulonglong2 wrz = *(const ulonglong2*)&Wp[k * WKF + wrzOff];
            ull wn = *(const ull*)&Wp[k * WKF + wnOff];
            float4 hq = *(const float4*)&hw[k * 4];
            ull hp[4] = {pk2(hq.x), pk2(hq.y), pk2(hq.z), pk2(hq.w)};
            #pragma unroll
            for (int v = 0; v < 4; v++) {
                acc[0][v] = ff2(hp[v], wrz.x, acc[0][v]);
                acc[1][v] = ff2(hp[v], wrz.y, acc[1][v]);
                acc[2][v] = ff2(hp[v], wn,    acc[2][v]);
            }
        }

        // ---- gates in-register (LIVE LANES ONLY — dead-lane hw[c*4] is OOB) ----
        float hn0[4], hn1[4];
        if (live) {
            float4 ho0 = *(const float4*)&hw[c * 4];
            float4 ho1 = *(const float4*)&hw[(c + 1) * 4];
            const float* o0 = (const float*)&ho0;
            const float* o1 = (const float*)&ho1;
            #pragma unroll
            for (int v = 0; v < 4; v++) {
                float2 sr = up2(acc[0][v]);
                float2 sz = up2(acc[1][v]);
                float2 sn = up2(acc[2][v]);
                float2 gi = up2(gis[v]);
                float r0 = fsig(sr.x), z0 = fsig(sz.x);
                float n0 = tanhapx(sn.x + (r0 - 1.0f) * (sn.x - gi.x));
                hn0[v] = n0 + z0 * (o0[v] - n0);
                float r1 = fsig(sr.y), z1 = fsig(sz.y);
                float n1 = tanhapx(sn.y + (r1 - 1.0f) * (sn.y - gi.y));
                hn1[v] = n1 + z1 * (o1[v] - n1);
            }
        }

        __syncwarp();   // all lanes done READING hs for step t
        if (live) {
            *(float4*)&hw[c * 4]       = make_float4(hn0[0], hn0[1], hn0[2], hn0[3]);
            *(float4*)&hw[(c + 1) * 4] = make_float4(hn1[0], hn1[1], hn1[2], hn1[3]);
        }
        if (t + 1 < TLEN) hw[HID * 4 + lane] = xv;             // publish x(t+1)
        if (t + 2 < TLEN) xv = xg[(size_t)(t + 2) * IN_DIM];   // prefetch x(t+2)
        __syncwarp();   // writes visible before step t+1 reads
    }

    // ---- linear head: lanes 0-3 handle the warp's 4 batches ----
    if (lane < 4) {
        float a = b_out[0];
        #pragma unroll
        for (int cc = 0; cc < HID; cc++) a += hw[cc * 4 + lane] * W_out[cc];
        out[b0w + lane] = a;
    }
}

extern "C" void kernel_launch(void* const* d_in, const int* in_sizes, int n_in,
                              void* d_out, int out_size) {
    const float* x     = (const float*)d_in[0];
    const float* W_ih  = (const float*)d_in[1];
    const float* W_hh  = (const float*)d_in[2];
    const float* b_ih  = (const float*)d_in[3];
    const float* b_hh  = (const float*)d_in[4];
    const float* W_out = (const float*)d_in[5];
    const float* b_out = (const float*)d_in[6];
    float* out = (float*)d_out;

    size_t smem = (size_t)(HID * WKF + 8 * HSW) * sizeof(float);
    cudaFuncSetAttribute(gru_kernel,
                         cudaFuncAttributeMaxDynamicSharedMemorySize, (int)smem);
    gru_kernel<<<GRIDN, NT, smem>>>(x, W_ih, W_hh, b_ih, b_hh, W_out, b_out, out);
}